// round 1
// baseline (speedup 1.0000x reference)
#include <cuda_runtime.h>

#define D_MODEL     2048
#define NUM_EXPERTS 64
#define N_TOKENS    16384
#define BM          128
#define BK          32
#define KSPLIT      4
#define KCHUNK      (D_MODEL / KSPLIT)   // 512
#define THREADS     128

// K-split partial logits: [KSPLIT][N_TOKENS][NUM_EXPERTS] fp32 (16 MB, static scratch)
__device__ float g_partial[KSPLIT * N_TOKENS * NUM_EXPERTS];

__device__ __forceinline__ unsigned long long ffma2(unsigned long long a,
                                                    unsigned long long b,
                                                    unsigned long long c) {
    unsigned long long d;
    asm("fma.rn.f32x2 %0, %1, %2, %3;" : "=l"(d) : "l"(a), "l"(b), "l"(c));
    return d;
}

// ---------------------------------------------------------------------------
// Kernel 1: logits GEMM. C[16384, 64] = X[16384, 2048] @ W^T[2048, 64]
// blockIdx.x: 128-token M tile (128 tiles); blockIdx.y: K split (4)
// Thread tile: 8 tokens (4 f32x2 pairs) x 8 experts (stride-8 interleave)
// ---------------------------------------------------------------------------
__global__ __launch_bounds__(THREADS)
void router_gemm(const float* __restrict__ X, const float* __restrict__ W) {
    // smem carve: Xs[k][t]  : 32 x 130 floats (pad 2 -> 8B-aligned rows, low conflicts)
    //             Ws2[k][e] : 32 x 65 float2  (duplicated (w,w) pairs)
    // total 8320 floats = 33280 B; reused as logits stage L[128][65] in epilogue
    __shared__ float smem[8320];
    float*  Xs  = smem;                        // index: k*130 + t
    float2* Ws2 = (float2*)(smem + 4160);      // index: k*65  + e

    const int tid    = threadIdx.x;
    const int token0 = blockIdx.x * BM;
    const int k_base = blockIdx.y * KCHUNK;

    const int tcol = tid & 7;    // experts: e = tcol + 8*j, j = 0..7
    const int trow = tid >> 3;   // tokens:  trow*8 .. trow*8+7

    unsigned long long acc[4][8];
    #pragma unroll
    for (int p = 0; p < 4; p++)
        #pragma unroll
        for (int j = 0; j < 8; j++) acc[p][j] = 0ULL;

    for (int kt = 0; kt < KCHUNK; kt += BK) {
        const int k0 = k_base + kt;

        // ---- load X tile (128 tokens x 32 k), transposed into Xs[k][t] ----
        #pragma unroll
        for (int r = 0; r < 8; r++) {
            int id = r * THREADS + tid;          // 0..1023
            int t  = id >> 3;
            int kg = (id & 7) * 4;
            float4 v = *(const float4*)(X + (size_t)(token0 + t) * D_MODEL + k0 + kg);
            Xs[(kg + 0) * 130 + t] = v.x;
            Xs[(kg + 1) * 130 + t] = v.y;
            Xs[(kg + 2) * 130 + t] = v.z;
            Xs[(kg + 3) * 130 + t] = v.w;
        }
        // ---- load W tile (64 e x 32 k), transposed + duplicated Ws2[k][e]=(w,w) ----
        #pragma unroll
        for (int r = 0; r < 4; r++) {
            int id = r * THREADS + tid;          // 0..511
            int e  = id >> 3;
            int kg = (id & 7) * 4;
            float4 v = *(const float4*)(W + (size_t)e * D_MODEL + k0 + kg);
            Ws2[(kg + 0) * 65 + e] = make_float2(v.x, v.x);
            Ws2[(kg + 1) * 65 + e] = make_float2(v.y, v.y);
            Ws2[(kg + 2) * 65 + e] = make_float2(v.z, v.z);
            Ws2[(kg + 3) * 65 + e] = make_float2(v.w, v.w);
        }
        __syncthreads();

        // ---- compute: 32 FFMA2 per k per thread ----
        #pragma unroll 8
        for (int k = 0; k < BK; k++) {
            unsigned long long xv[4], wv[8];
            #pragma unroll
            for (int p = 0; p < 4; p++)
                xv[p] = *(const unsigned long long*)&Xs[k * 130 + trow * 8 + 2 * p];
            #pragma unroll
            for (int j = 0; j < 8; j++)
                wv[j] = *(const unsigned long long*)&Ws2[k * 65 + tcol + 8 * j];
            #pragma unroll
            for (int p = 0; p < 4; p++)
                #pragma unroll
                for (int j = 0; j < 8; j++)
                    acc[p][j] = ffma2(xv[p], wv[j], acc[p][j]);
        }
        __syncthreads();
    }

    // ---- epilogue: stage logits in smem, then coalesced store to scratch ----
    float* L = smem;   // L[t][e] at t*65 + e (8320 floats, fits exactly)
    #pragma unroll
    for (int p = 0; p < 4; p++) {
        #pragma unroll
        for (int j = 0; j < 8; j++) {
            float2 v = *reinterpret_cast<float2*>(&acc[p][j]);
            int e = tcol + 8 * j;
            int t = trow * 8 + 2 * p;
            L[(t + 0) * 65 + e] = v.x;
            L[(t + 1) * 65 + e] = v.y;
        }
    }
    __syncthreads();

    float* out = g_partial + ((size_t)blockIdx.y * N_TOKENS + token0) * NUM_EXPERTS;
    #pragma unroll 4
    for (int i = tid; i < BM * NUM_EXPERTS; i += THREADS) {
        int t = i >> 6, e = i & 63;
        out[(size_t)t * NUM_EXPERTS + e] = L[t * 65 + e];
    }
}

// ---------------------------------------------------------------------------
// Kernel 2: reduce K-split partials + bias, warp top-2 (jax tie-break:
// lower index first on equal values), renormalized softmax weights.
// One warp per token; 8 tokens per 256-thread CTA.
// ---------------------------------------------------------------------------
__device__ __forceinline__ bool better(float x, int ix, float y, int iy) {
    return (x > y) || (x == y && ix < iy);
}

__global__ __launch_bounds__(256)
void router_topk(const float* __restrict__ bias, float* __restrict__ out) {
    const int warp  = threadIdx.x >> 5;
    const int lane  = threadIdx.x & 31;
    const int token = blockIdx.x * 8 + warp;

    const int e0 = lane, e1 = lane + 32;
    float v0 = bias[e0], v1 = bias[e1];
    #pragma unroll
    for (int s = 0; s < KSPLIT; s++) {
        const float* p = g_partial + ((size_t)s * N_TOKENS + token) * NUM_EXPERTS;
        v0 += p[e0];
        v1 += p[e1];
    }

    float a, b; int ia, ib;
    if (v0 >= v1) { a = v0; ia = e0; b = v1; ib = e1; }   // tie -> lower index (e0)
    else          { a = v1; ia = e1; b = v0; ib = e0; }

    #pragma unroll
    for (int off = 16; off; off >>= 1) {
        float oa  = __shfl_xor_sync(0xffffffffu, a, off);
        int   oia = __shfl_xor_sync(0xffffffffu, ia, off);
        float ob  = __shfl_xor_sync(0xffffffffu, b, off);
        int   oib = __shfl_xor_sync(0xffffffffu, ib, off);
        if (better(oa, oia, a, ia)) {
            // other's top wins: swap tops, adopt other's second
            float ta = a; int tia = ia;
            a = oa; ia = oia;
            oa = ta; oia = tia;       // oa/oia now the losing top
            b = ob; ib = oib;
        }
        // second = better of (winner's second) and (losing top)
        if (better(oa, oia, b, ib)) { b = oa; ib = oia; }
    }

    if (lane == 0) {
        // normalized top-2 of softmax == pairwise logistic of logits
        float r  = expf(b - a);               // <= 1
        float w1 = 1.0f / (1.0f + r);
        float w2 = r / (1.0f + r);
        out[token * 2 + 0] = w1;
        out[token * 2 + 1] = w2;
        out[N_TOKENS * 2 + token * 2 + 0] = (float)ia;
        out[N_TOKENS * 2 + token * 2 + 1] = (float)ib;
    }
}

// ---------------------------------------------------------------------------
extern "C" void kernel_launch(void* const* d_in, const int* in_sizes, int n_in,
                              void* d_out, int out_size) {
    const float* X = (const float*)d_in[0];   // [4, 4096, 2048]
    const float* W = (const float*)d_in[1];   // [64, 2048]
    const float* b = (const float*)d_in[2];   // [64]
    float* out = (float*)d_out;               // [2*16384] weights ++ [2*16384] indices

    dim3 grid1(N_TOKENS / BM, KSPLIT);        // 128 x 4 = 512 CTAs
    router_gemm<<<grid1, THREADS>>>(X, W);
    router_topk<<<N_TOKENS / 8, 256>>>(b, out);
}